// round 9
// baseline (speedup 1.0000x reference)
#include <cuda_runtime.h>
#include <math.h>
#include <stdio.h>
#include <assert.h>

#define Vv 30000
#define Ee 300
#define Hd 300
#define Td 9
#define Bd 256
#define Sd 256

// ---- scratch ----
__device__ float  g_hf[(size_t)Sd * Bd * Hd];
__device__ float  g_hb[(size_t)Sd * Bd * Hd];
__device__ float  g_cf[Bd * Hd];
__device__ float  g_cb[Bd * Hd];
__device__ double g_em[(size_t)Sd * Bd * Td];            // fp64 emissions
__device__ unsigned char g_bp[(size_t)(Sd - 1) * Bd * Td];

__device__ __forceinline__ float clampg(float v) {
    return fmaxf(fminf(v, 30.f), -30.f);
}

struct SizePack { int n; int v[16]; };
__global__ void bad_layout_kernel(SizePack sp)
{
    printf("[diag] LAYOUT MISMATCH n_in=%d sizes:", sp.n);
    for (int i = 0; i < 16 && i < sp.n; i++) printf(" %d", sp.v[i]);
    printf("\n");
    assert(0);
}

// ============================================================
// One LSTM time step, both directions; input GEMM fused.
// A = [emb[token] | h_prev], K = 600. Tile 32b x 32h x 4g.
// (numerics independently verified in R7 against fp64 recompute)
// ============================================================
__global__ void __launch_bounds__(256)
lstm_step(int s, const int* __restrict__ x, const float* __restrict__ emb,
          const float* __restrict__ wihf, const float* __restrict__ whhf,
          const float* __restrict__ wihb, const float* __restrict__ whhb,
          const float* __restrict__ bihf, const float* __restrict__ bhhf,
          const float* __restrict__ bihb, const float* __restrict__ bhhb)
{
    int dir = blockIdx.z;
    const float* wih = dir ? wihb : wihf;
    const float* whh = dir ? whhb : whhf;
    const float* b1  = dir ? bihb : bihf;
    const float* b2  = dir ? bhhb : bhhf;
    float* hseq = dir ? g_hb : g_hf;
    float* cbuf = dir ? g_cb : g_cf;
    int time = dir ? (Sd - 1 - s) : s;
    float* hout = hseq + (size_t)time * Bd * Hd;
    const float* hprev = (s > 0)
        ? hseq + (size_t)(dir ? time + 1 : time - 1) * Bd * Hd : (const float*)0;

    int h0 = blockIdx.x * 32;
    int b0 = blockIdx.y * 32;
    int tid = threadIdx.x;
    int tx = tid & 31;
    int ty = tid >> 5;

    __shared__ int   sh_tok[32];
    __shared__ float sh_a[32][33];
    __shared__ float sh_w[4][32][33];

    if (tid < 32) {
        int t = x[(b0 + tid) * Sd + time];
        sh_tok[tid] = ((unsigned)t < (unsigned)Vv) ? t : 0;
    }
    __syncthreads();

    float acc[4][4] = {};
    int kmax = (s > 0) ? (Ee + Hd) : Ee;

    for (int k0 = 0; k0 < kmax; k0 += 32) {
#pragma unroll
        for (int i = 0; i < 4; i++) {
            int l = tid + 256 * i;
            int r = l >> 5, c = l & 31;
            int k = k0 + c;
            float v = 0.f;
            if (k < Ee)
                v = emb[(size_t)sh_tok[r] * Ee + k];
            else if (k < Ee + Hd && s > 0)
                v = hprev[(size_t)(b0 + r) * Hd + (k - Ee)];
            sh_a[r][c] = v;
        }
#pragma unroll
        for (int i = 0; i < 16; i++) {
            int l = tid + 256 * i;
            int g = l >> 10;
            int r = (l >> 5) & 31;
            int c = l & 31;
            int n = h0 + r;
            int k = k0 + c;
            float v = 0.f;
            if (n < Hd) {
                if (k < Ee)
                    v = wih[(size_t)(g * Hd + n) * Ee + k];
                else if (k < Ee + Hd)
                    v = whh[(size_t)(g * Hd + n) * Hd + (k - Ee)];
            }
            sh_w[g][r][c] = v;
        }
        __syncthreads();
#pragma unroll
        for (int kk = 0; kk < 32; kk++) {
            float wv[4];
#pragma unroll
            for (int g = 0; g < 4; g++) wv[g] = sh_w[g][tx][kk];
#pragma unroll
            for (int i = 0; i < 4; i++) {
                float hv = sh_a[ty + 8 * i][kk];
#pragma unroll
                for (int g = 0; g < 4; g++) acc[i][g] += hv * wv[g];
            }
        }
        __syncthreads();
    }

    int h = h0 + tx;
    if (h < Hd) {
        float bi = b1[h]          + b2[h];
        float bf = b1[Hd + h]     + b2[Hd + h];
        float bg = b1[2 * Hd + h] + b2[2 * Hd + h];
        float bo = b1[3 * Hd + h] + b2[3 * Hd + h];
#pragma unroll
        for (int i = 0; i < 4; i++) {
            int b = b0 + ty + 8 * i;
            float ai = clampg(acc[i][0] + bi);
            float af = clampg(acc[i][1] + bf);
            float ag = clampg(acc[i][2] + bg);
            float ao = clampg(acc[i][3] + bo);
            float cold = (s == 0) ? 0.f : cbuf[(size_t)b * Hd + h];
            float ig = 1.f / (1.f + expf(-ai));
            float fg = 1.f / (1.f + expf(-af));
            float gg = tanhf(ag);
            float og = 1.f / (1.f + expf(-ao));
            float cnew = fg * cold + ig * gg;
            float hnew = og * tanhf(clampg(cnew));
            cbuf[(size_t)b * Hd + h] = cnew;
            hout[(size_t)b * Hd + h] = hnew;
        }
    }
}

// ============================================================
// Emissions with FP64 accumulation. One warp per (s,b).
// ============================================================
__global__ void __launch_bounds__(256)
emis_kernel(const float* __restrict__ wproj, const float* __restrict__ bproj)
{
    int warp = (blockIdx.x * blockDim.x + threadIdx.x) >> 5;
    int lane = threadIdx.x & 31;
    if (warp >= Sd * Bd) return;
    int s = warp / Bd, b = warp % Bd;
    const float* f  = g_hf + ((size_t)s * Bd + b) * Hd;
    const float* bk = g_hb + ((size_t)s * Bd + b) * Hd;
    double acc[Td] = {};
    for (int j = lane; j < 2 * Hd; j += 32) {
        double v = (j < Hd) ? (double)f[j] : (double)bk[j - Hd];
#pragma unroll
        for (int t = 0; t < Td; t++) acc[t] += v * (double)wproj[t * 2 * Hd + j];
    }
#pragma unroll
    for (int t = 0; t < Td; t++) {
        double a = acc[t];
#pragma unroll
        for (int o = 16; o > 0; o >>= 1) a += __shfl_xor_sync(0xffffffffu, a, o);
        if (lane == 0) g_em[((size_t)s * Bd + b) * Td + t] = a + (double)bproj[t];
    }
}

// ============================================================
// Viterbi DP + backtrack, FP64. One thread per batch row.
// *** Output written as FLOAT32 tag values (the fix) ***
// ============================================================
__global__ void viterbi_kernel(const float* __restrict__ start_t, const float* __restrict__ end_t,
                               const float* __restrict__ trans, float* __restrict__ out)
{
    __shared__ double tr[Td][Td];
    if (threadIdx.x < Td * Td)
        tr[threadIdx.x / Td][threadIdx.x % Td] = (double)trans[threadIdx.x];
    __syncthreads();
    int b = blockIdx.x * blockDim.x + threadIdx.x;
    if (b >= Bd) return;

    double sc[Td];
#pragma unroll
    for (int t = 0; t < Td; t++)
        sc[t] = (double)start_t[t] + g_em[(size_t)b * Td + t];

    for (int s = 1; s < Sd; s++) {
        const double* em = &g_em[((size_t)s * Bd + b) * Td];
        double ns[Td];
#pragma unroll
        for (int tn = 0; tn < Td; tn++) {
            double best = sc[0] + tr[0][tn];
            int arg = 0;
#pragma unroll
            for (int tp = 1; tp < Td; tp++) {
                double v = sc[tp] + tr[tp][tn];
                if (v > best) { best = v; arg = tp; }
            }
            ns[tn] = best + em[tn];
            g_bp[((size_t)(s - 1) * Bd + b) * Td + tn] = (unsigned char)arg;
        }
#pragma unroll
        for (int t = 0; t < Td; t++) sc[t] = ns[t];
    }

    int last = 0;
    double best = sc[0] + (double)end_t[0];
#pragma unroll
    for (int t = 1; t < Td; t++) {
        double v = sc[t] + (double)end_t[t];
        if (v > best) { best = v; last = t; }
    }
    out[b * Sd + (Sd - 1)] = (float)last;
    int tag = last;
    for (int s = Sd - 2; s >= 0; s--) {
        tag = g_bp[((size_t)s * Bd + b) * Td + tag];
        out[b * Sd + s] = (float)tag;
    }
}

// ============================================================
extern "C" void kernel_launch(void* const* d_in, const int* in_sizes, int n_in,
                              void* d_out, int out_size)
{
    static const int expA[15] = {65536, 9000000, 360000, 360000, 1200, 1200,
                                 360000, 360000, 1200, 1200, 5400, 9, 9, 9, 81};
    bool okA = (n_in == 15), okA4 = (n_in == 15);
    for (int i = 0; i < 15 && n_in == 15; i++) {
        if (in_sizes[i] != expA[i])     okA  = false;
        if (in_sizes[i] != expA[i] * 4) okA4 = false;
    }
    if (!okA && !okA4) {
        SizePack sp; sp.n = n_in;
        for (int i = 0; i < 16; i++) sp.v[i] = (i < n_in) ? in_sizes[i] : -1;
        bad_layout_kernel<<<1, 1>>>(sp);
        return;
    }

    const int*   x       = (const int*)  d_in[0];
    const float* emb     = (const float*)d_in[1];
    const float* wihf    = (const float*)d_in[2];
    const float* whhf    = (const float*)d_in[3];
    const float* bihf    = (const float*)d_in[4];
    const float* bhhf    = (const float*)d_in[5];
    const float* wihb    = (const float*)d_in[6];
    const float* whhb    = (const float*)d_in[7];
    const float* bihb    = (const float*)d_in[8];
    const float* bhhb    = (const float*)d_in[9];
    const float* wproj   = (const float*)d_in[10];
    const float* bproj   = (const float*)d_in[11];
    const float* start_t = (const float*)d_in[12];
    const float* end_t   = (const float*)d_in[13];
    const float* trans   = (const float*)d_in[14];
    float* out = (float*)d_out;   // __output__ treated as float32

    dim3 gs((Hd + 31) / 32, Bd / 32, 2);
    for (int s = 0; s < Sd; s++)
        lstm_step<<<gs, 256>>>(s, x, emb, wihf, whhf, wihb, whhb,
                               bihf, bhhf, bihb, bhhb);

    emis_kernel<<<(Sd * Bd * 32) / 256, 256>>>(wproj, bproj);
    viterbi_kernel<<<2, 128>>>(start_t, end_t, trans, out);
}

// round 10
// speedup vs baseline: 3.1117x; 3.1117x over previous
#include <cuda_runtime.h>
#include <math.h>
#include <stdio.h>
#include <assert.h>

#define Vv 30000
#define Ee 300
#define Hd 300
#define G4 1200
#define Td 9
#define Bd 256
#define Sd 256

// ---- scratch (device globals) ----
__device__ float  g_table_f[(size_t)Vv * G4];   // emb@w_ih_f^T + (b_ih+b_hh)  [V,1200]
__device__ float  g_table_b[(size_t)Vv * G4];
__device__ float  g_hf[(size_t)Sd * Bd * Hd];
__device__ float  g_hb[(size_t)Sd * Bd * Hd];
__device__ float  g_cf[Bd * Hd];
__device__ float  g_cb[Bd * Hd];
__device__ double g_em[(size_t)Sd * Bd * Td];
__device__ unsigned char g_bp[(size_t)(Sd - 1) * Bd * Td];

__device__ __forceinline__ float clampg(float v) {
    return fmaxf(fminf(v, 30.f), -30.f);
}

struct SizePack { int n; int v[16]; };
__global__ void bad_layout_kernel(SizePack sp)
{
    printf("[diag] LAYOUT MISMATCH n_in=%d sizes:", sp.n);
    for (int i = 0; i < 16 && i < sp.n; i++) printf(" %d", sp.v[i]);
    printf("\n");
    assert(0);
}

// ============================================================
// Phase 1: vocab gate table. C[m][n] = sum_k emb[m][k]*W[n][k] + b1[n]+b2[n]
// M=30000, N=1200, K=300. Tile 64x64, 256 thr, 4x4 micro, float4 smem reads.
// ============================================================
__global__ void __launch_bounds__(256)
table_gemm(const float* __restrict__ A, const float* __restrict__ W,
           const float* __restrict__ b1, const float* __restrict__ b2, int dir)
{
    __shared__ __align__(16) float As[32][68];
    __shared__ __align__(16) float Ws[32][68];
    float* C = dir ? g_table_b : g_table_f;

    int m0 = blockIdx.y * 64;
    int n0 = blockIdx.x * 64;
    int tid = threadIdx.x;
    int tx = tid & 15, ty = tid >> 4;
    float acc[4][4] = {};

    for (int k0 = 0; k0 < Ee; k0 += 32) {
#pragma unroll
        for (int i = 0; i < 8; i++) {
            int idx = tid + 256 * i;          // 0..2047
            int r = idx >> 5, c = idx & 31;
            int k = k0 + c;
            int m = m0 + r;
            As[c][r] = (m < Vv && k < Ee) ? A[(size_t)m * Ee + k] : 0.f;
            int n = n0 + r;
            Ws[c][r] = (n < G4 && k < Ee) ? W[(size_t)n * Ee + k] : 0.f;
        }
        __syncthreads();
#pragma unroll
        for (int kk = 0; kk < 32; kk++) {
            float4 a4 = *(const float4*)&As[kk][ty * 4];
            float4 w4 = *(const float4*)&Ws[kk][tx * 4];
            float av[4] = {a4.x, a4.y, a4.z, a4.w};
            float wv[4] = {w4.x, w4.y, w4.z, w4.w};
#pragma unroll
            for (int i = 0; i < 4; i++)
#pragma unroll
                for (int j = 0; j < 4; j++) acc[i][j] += av[i] * wv[j];
        }
        __syncthreads();
    }

    int nbase = n0 + tx * 4;
    float bias[4];
#pragma unroll
    for (int j = 0; j < 4; j++) {
        int n = nbase + j;
        bias[j] = (n < G4) ? (b1[n] + b2[n]) : 0.f;
    }
#pragma unroll
    for (int i = 0; i < 4; i++) {
        int m = m0 + ty * 4 + i;
        if (m >= Vv) continue;
        if (nbase + 3 < G4) {
            float4 o = make_float4(acc[i][0] + bias[0], acc[i][1] + bias[1],
                                   acc[i][2] + bias[2], acc[i][3] + bias[3]);
            *(float4*)&C[(size_t)m * G4 + nbase] = o;
        } else {
#pragma unroll
            for (int j = 0; j < 4; j++)
                if (nbase + j < G4) C[(size_t)m * G4 + nbase + j] = acc[i][j] + bias[j];
        }
    }
}

// ============================================================
// Phase 2: recurrent step, h @ w_hh^T only (x-part comes from the table).
// Tile: 64 b x 16 h x 4 gates. Gate-interleaved smem W so one float4 =
// 4 gates of one h. 2x LDS.128 per 16 FFMA.
// ============================================================
__global__ void __launch_bounds__(256)
lstm_step(int s, const int* __restrict__ x,
          const float* __restrict__ whhf, const float* __restrict__ whhb)
{
    int dir = blockIdx.z;
    const float* whh = dir ? whhb : whhf;
    const float* tbl = dir ? g_table_b : g_table_f;
    float* hseq = dir ? g_hb : g_hf;
    float* cbuf = dir ? g_cb : g_cf;
    int time = dir ? (Sd - 1 - s) : s;
    float* hout = hseq + (size_t)time * Bd * Hd;

    int h0 = blockIdx.x * 16;
    int b0 = blockIdx.y * 64;
    int tid = threadIdx.x;
    int tx = tid & 15;   // h_local
    int ty = tid >> 4;   // b quad (0..15)

    __shared__ __align__(16) float Hs[32][68];
    __shared__ __align__(16) float Ws[32][68];
    __shared__ int toks[64];

    if (tid < 64) {
        int t = x[(b0 + tid) * Sd + time];
        toks[tid] = ((unsigned)t < (unsigned)Vv) ? t : 0;
    }

    float acc[4][4] = {};   // [b_i][gate]

    if (s > 0) {
        const float* hprev = hseq + (size_t)(dir ? time + 1 : time - 1) * Bd * Hd;
        for (int k0 = 0; k0 < Hd; k0 += 32) {
#pragma unroll
            for (int i = 0; i < 8; i++) {
                int idx = tid + 256 * i;      // 0..2047
                int r = idx >> 5, c = idx & 31;
                int k = k0 + c;
                // H tile: rows = 64 batch entries
                Hs[c][r] = (k < Hd) ? hprev[(size_t)(b0 + r) * Hd + k] : 0.f;
                // W tile: q = r encodes (gate, h_local); store gate-interleaved
                int g = r >> 4, hl = r & 15;
                int hh = h0 + hl;
                Ws[c][hl * 4 + g] = (hh < Hd && k < Hd)
                    ? whh[(size_t)(g * Hd + hh) * Hd + k] : 0.f;
            }
            __syncthreads();
#pragma unroll
            for (int kk = 0; kk < 32; kk++) {
                float4 h4 = *(const float4*)&Hs[kk][ty * 4];
                float4 w4 = *(const float4*)&Ws[kk][tx * 4];
                float hv[4] = {h4.x, h4.y, h4.z, h4.w};
                float wv[4] = {w4.x, w4.y, w4.z, w4.w};
#pragma unroll
                for (int i = 0; i < 4; i++)
#pragma unroll
                    for (int g = 0; g < 4; g++) acc[i][g] += hv[i] * wv[g];
            }
            __syncthreads();
        }
    } else {
        __syncthreads();   // make toks visible
    }

    int h = h0 + tx;
    if (h < Hd) {
#pragma unroll
        for (int i = 0; i < 4; i++) {
            int b = b0 + ty * 4 + i;
            const float* trow = tbl + (size_t)toks[ty * 4 + i] * G4;
            float ai = clampg(acc[i][0] + trow[h]);
            float af = clampg(acc[i][1] + trow[Hd + h]);
            float ag = clampg(acc[i][2] + trow[2 * Hd + h]);
            float ao = clampg(acc[i][3] + trow[3 * Hd + h]);
            float cold = (s == 0) ? 0.f : cbuf[(size_t)b * Hd + h];
            float ig = 1.f / (1.f + expf(-ai));
            float fg = 1.f / (1.f + expf(-af));
            float gg = tanhf(ag);
            float og = 1.f / (1.f + expf(-ao));
            float cnew = fg * cold + ig * gg;
            float hnew = og * tanhf(clampg(cnew));
            cbuf[(size_t)b * Hd + h] = cnew;
            hout[(size_t)b * Hd + h] = hnew;
        }
    }
}

// ============================================================
// Emissions with FP64 accumulation. One warp per (s,b).
// ============================================================
__global__ void __launch_bounds__(256)
emis_kernel(const float* __restrict__ wproj, const float* __restrict__ bproj)
{
    int warp = (blockIdx.x * blockDim.x + threadIdx.x) >> 5;
    int lane = threadIdx.x & 31;
    if (warp >= Sd * Bd) return;
    int s = warp / Bd, b = warp % Bd;
    const float* f  = g_hf + ((size_t)s * Bd + b) * Hd;
    const float* bk = g_hb + ((size_t)s * Bd + b) * Hd;
    double acc[Td] = {};
    for (int j = lane; j < 2 * Hd; j += 32) {
        double v = (j < Hd) ? (double)f[j] : (double)bk[j - Hd];
#pragma unroll
        for (int t = 0; t < Td; t++) acc[t] += v * (double)wproj[t * 2 * Hd + j];
    }
#pragma unroll
    for (int t = 0; t < Td; t++) {
        double a = acc[t];
#pragma unroll
        for (int o = 16; o > 0; o >>= 1) a += __shfl_xor_sync(0xffffffffu, a, o);
        if (lane == 0) g_em[((size_t)s * Bd + b) * Td + t] = a + (double)bproj[t];
    }
}

// ============================================================
// Viterbi DP + backtrack, FP64. Output written as FLOAT32 tags.
// ============================================================
__global__ void viterbi_kernel(const float* __restrict__ start_t, const float* __restrict__ end_t,
                               const float* __restrict__ trans, float* __restrict__ out)
{
    __shared__ double tr[Td][Td];
    if (threadIdx.x < Td * Td)
        tr[threadIdx.x / Td][threadIdx.x % Td] = (double)trans[threadIdx.x];
    __syncthreads();
    int b = blockIdx.x * blockDim.x + threadIdx.x;
    if (b >= Bd) return;

    double sc[Td];
#pragma unroll
    for (int t = 0; t < Td; t++)
        sc[t] = (double)start_t[t] + g_em[(size_t)b * Td + t];

    for (int s = 1; s < Sd; s++) {
        const double* em = &g_em[((size_t)s * Bd + b) * Td];
        double ns[Td];
#pragma unroll
        for (int tn = 0; tn < Td; tn++) {
            double best = sc[0] + tr[0][tn];
            int arg = 0;
#pragma unroll
            for (int tp = 1; tp < Td; tp++) {
                double v = sc[tp] + tr[tp][tn];
                if (v > best) { best = v; arg = tp; }
            }
            ns[tn] = best + em[tn];
            g_bp[((size_t)(s - 1) * Bd + b) * Td + tn] = (unsigned char)arg;
        }
#pragma unroll
        for (int t = 0; t < Td; t++) sc[t] = ns[t];
    }

    int last = 0;
    double best = sc[0] + (double)end_t[0];
#pragma unroll
    for (int t = 1; t < Td; t++) {
        double v = sc[t] + (double)end_t[t];
        if (v > best) { best = v; last = t; }
    }
    out[b * Sd + (Sd - 1)] = (float)last;
    int tag = last;
    for (int s = Sd - 2; s >= 0; s--) {
        tag = g_bp[((size_t)s * Bd + b) * Td + tag];
        out[b * Sd + s] = (float)tag;
    }
}

// ============================================================
extern "C" void kernel_launch(void* const* d_in, const int* in_sizes, int n_in,
                              void* d_out, int out_size)
{
    static const int expA[15] = {65536, 9000000, 360000, 360000, 1200, 1200,
                                 360000, 360000, 1200, 1200, 5400, 9, 9, 9, 81};
    bool okA = (n_in == 15), okA4 = (n_in == 15);
    for (int i = 0; i < 15 && n_in == 15; i++) {
        if (in_sizes[i] != expA[i])     okA  = false;
        if (in_sizes[i] != expA[i] * 4) okA4 = false;
    }
    if (!okA && !okA4) {
        SizePack sp; sp.n = n_in;
        for (int i = 0; i < 16; i++) sp.v[i] = (i < n_in) ? in_sizes[i] : -1;
        bad_layout_kernel<<<1, 1>>>(sp);
        return;
    }

    const int*   x       = (const int*)  d_in[0];
    const float* emb     = (const float*)d_in[1];
    const float* wihf    = (const float*)d_in[2];
    const float* whhf    = (const float*)d_in[3];
    const float* bihf    = (const float*)d_in[4];
    const float* bhhf    = (const float*)d_in[5];
    const float* wihb    = (const float*)d_in[6];
    const float* whhb    = (const float*)d_in[7];
    const float* bihb    = (const float*)d_in[8];
    const float* bhhb    = (const float*)d_in[9];
    const float* wproj   = (const float*)d_in[10];
    const float* bproj   = (const float*)d_in[11];
    const float* start_t = (const float*)d_in[12];
    const float* end_t   = (const float*)d_in[13];
    const float* trans   = (const float*)d_in[14];
    float* out = (float*)d_out;

    // Phase 1: vocab gate tables (hoists x-side GEMM out of the chain)
    dim3 gt((G4 + 63) / 64, (Vv + 63) / 64);
    table_gemm<<<gt, 256>>>(emb, wihf, bihf, bhhf, 0);
    table_gemm<<<gt, 256>>>(emb, wihb, bihb, bhhb, 1);

    // Phase 2: 256 recurrent steps (fwd+bwd per launch), h@w_hh only
    dim3 gs((Hd + 15) / 16, Bd / 64, 2);
    for (int s = 0; s < Sd; s++)
        lstm_step<<<gs, 256>>>(s, x, whhf, whhb);

    // Phase 3: emissions + Viterbi
    emis_kernel<<<(Sd * Bd * 32) / 256, 256>>>(wproj, bproj);
    viterbi_kernel<<<2, 128>>>(start_t, end_t, trans, out);
}